// round 11
// baseline (speedup 1.0000x reference)
#include <cuda_runtime.h>
#include <cuda_bf16.h>

// Problem constants (fixed by the reference).
#define B_DIM   64
#define H_DIM   512
#define W_DIM   640
#define P_DIM   100000
#define TOTAL   (B_DIM * P_DIM)     // 6,400,000 points
#define HW      (H_DIM * W_DIM)     // 327,680
#define NV4     (TOTAL / 4)         // 1,600,000 vec4 groups
#define HALF    (NV4 / 2)           // 800,000 vec4-pairs = total threads
#define THREADS 256
#define BLOCKS  (HALF / THREADS)    // 3125 (exact)

// Cross-launch scratch for single-kernel finalization. Statically zero.
__device__ float        g_partial = 0.0f;
__device__ unsigned int g_done    = 0u;

__device__ __forceinline__ float loss_pt(float za, float zb, int od) {
    const float zd = za - zb;
    // gt = od-1 in {-1,0,1}; sign only matters when od != 1.
    const float t  = fminf((od >= 2) ? zd : -zd, 1.0f);
    const float l1 = __logf(1.0f + __expf(-t));
    const float l2 = fmaxf(zd * zd, 1.0f);
    return (od == 1) ? l2 : l1;
}

// 32 regs (validated R8) -> 8 blocks/SM, 64 warps, 100% theoretical occ.
// ALL loads are plain __ldg: the .cs evict-first variant adds ~600cyc of
// unhidden latency on the critical path (R5/R7/R8 evidence, ~+10us).
__global__ __launch_bounds__(THREADS, 8) void rd_loss_kernel(
    const float* __restrict__ depth,
    const int*   __restrict__ xA,
    const int*   __restrict__ yA,
    const int*   __restrict__ xB,
    const int*   __restrict__ yB,
    const int*   __restrict__ ord,
    float* __restrict__ out)
{
    const int t  = blockIdx.x * THREADS + threadIdx.x;
    const int v0 = t;            // first vec4 group
    const int v1 = t + HALF;     // second vec4 group (coalesced within warp)

    // ---- Issue ALL index loads first (10 coalesced int4 LDGs in flight) ----
    const int4 xa0 = __ldg((const int4*)xA  + v0);
    const int4 ya0 = __ldg((const int4*)yA  + v0);
    const int4 xb0 = __ldg((const int4*)xB  + v0);
    const int4 yb0 = __ldg((const int4*)yB  + v0);
    const int4 od0 = __ldg((const int4*)ord + v0);
    const int4 xa1 = __ldg((const int4*)xA  + v1);
    const int4 ya1 = __ldg((const int4*)yA  + v1);
    const int4 xb1 = __ldg((const int4*)xB  + v1);
    const int4 yb1 = __ldg((const int4*)yB  + v1);
    const int4 od1 = __ldg((const int4*)ord + v1);

    // Batch offsets as int32 (max offset 64*327680 < 2^25): single base ptr,
    // saves a 64-bit pointer pair per group (regs 40 -> 32).
    const int boff0 = ((v0 * 4) / P_DIM) * HW;
    const int boff1 = ((v1 * 4) / P_DIM) * HW;

    // ---- Issue ALL 16 gathers batched (max MLP) ----
    float zA[8], zB[8];
    zA[0] = __ldg(depth + (boff0 + ya0.x * W_DIM + xa0.x));
    zA[1] = __ldg(depth + (boff0 + ya0.y * W_DIM + xa0.y));
    zA[2] = __ldg(depth + (boff0 + ya0.z * W_DIM + xa0.z));
    zA[3] = __ldg(depth + (boff0 + ya0.w * W_DIM + xa0.w));
    zA[4] = __ldg(depth + (boff1 + ya1.x * W_DIM + xa1.x));
    zA[5] = __ldg(depth + (boff1 + ya1.y * W_DIM + xa1.y));
    zA[6] = __ldg(depth + (boff1 + ya1.z * W_DIM + xa1.z));
    zA[7] = __ldg(depth + (boff1 + ya1.w * W_DIM + xa1.w));
    zB[0] = __ldg(depth + (boff0 + yb0.x * W_DIM + xb0.x));
    zB[1] = __ldg(depth + (boff0 + yb0.y * W_DIM + xb0.y));
    zB[2] = __ldg(depth + (boff0 + yb0.z * W_DIM + xb0.z));
    zB[3] = __ldg(depth + (boff0 + yb0.w * W_DIM + xb0.w));
    zB[4] = __ldg(depth + (boff1 + yb1.x * W_DIM + xb1.x));
    zB[5] = __ldg(depth + (boff1 + yb1.y * W_DIM + xb1.y));
    zB[6] = __ldg(depth + (boff1 + yb1.z * W_DIM + xb1.z));
    zB[7] = __ldg(depth + (boff1 + yb1.w * W_DIM + xb1.w));

    // ---- Loss (two independent accumulation chains) ----
    float acc0 = 0.0f, acc1 = 0.0f;
    acc0 += loss_pt(zA[0], zB[0], od0.x);
    acc1 += loss_pt(zA[1], zB[1], od0.y);
    acc0 += loss_pt(zA[2], zB[2], od0.z);
    acc1 += loss_pt(zA[3], zB[3], od0.w);
    acc0 += loss_pt(zA[4], zB[4], od1.x);
    acc1 += loss_pt(zA[5], zB[5], od1.y);
    acc0 += loss_pt(zA[6], zB[6], od1.z);
    acc1 += loss_pt(zA[7], zB[7], od1.w);
    float acc = acc0 + acc1;

    // ---- Block reduction: warp shuffle, then smem across 8 warps ----
    __shared__ float warp_sums[THREADS / 32];
    const int lane = threadIdx.x & 31;
    const int wid  = threadIdx.x >> 5;
#pragma unroll
    for (int off = 16; off > 0; off >>= 1)
        acc += __shfl_xor_sync(0xFFFFFFFF, acc, off);
    if (lane == 0) warp_sums[wid] = acc;
    __syncthreads();

    if (threadIdx.x == 0) {
        float s = 0.0f;
#pragma unroll
        for (int w = 0; w < THREADS / 32; w++) s += warp_sums[w];

        // Accumulate into device scratch; last block finalizes and resets
        // the scratch so every graph replay starts from a clean state.
        atomicAdd(&g_partial, s);
        __threadfence();
        const unsigned done = atomicInc(&g_done, BLOCKS - 1);  // wraps to 0
        if (done == BLOCKS - 1) {
            const float total = atomicAdd(&g_partial, 0.0f);   // coherent read
            out[0] = total * (1.0f / (float)TOTAL);
            g_partial = 0.0f;                                  // reset for next replay
        }
    }
}

extern "C" void kernel_launch(void* const* d_in, const int* in_sizes, int n_in,
                              void* d_out, int out_size)
{
    const float* depth = (const float*)d_in[0];
    const int*   xA    = (const int*)d_in[1];
    const int*   yA    = (const int*)d_in[2];
    const int*   xB    = (const int*)d_in[3];
    const int*   yB    = (const int*)d_in[4];
    const int*   ord   = (const int*)d_in[5];
    float* out = (float*)d_out;

    rd_loss_kernel<<<BLOCKS, THREADS>>>(depth, xA, yA, xB, yB, ord, out);
}

// round 12
// speedup vs baseline: 1.0298x; 1.0298x over previous
#include <cuda_runtime.h>
#include <cuda_bf16.h>

// Problem constants (fixed by the reference).
#define B_DIM   64
#define H_DIM   512
#define W_DIM   640
#define P_DIM   100000
#define TOTAL   (B_DIM * P_DIM)     // 6,400,000 points
#define HW      (H_DIM * W_DIM)     // 327,680
#define NV4     (TOTAL / 4)         // 1,600,000 vec4 groups
#define HALF    (NV4 / 2)           // 800,000 vec4-pairs = total threads
#define THREADS 256
#define BLOCKS  (HALF / THREADS)    // 3125 (exact)

// Cross-launch scratch for single-kernel finalization. Statically zero.
__device__ float        g_partial = 0.0f;
__device__ unsigned int g_done    = 0u;

__device__ __forceinline__ float loss_pt(float za, float zb, int od) {
    const float zd = za - zb;
    // gt = od-1 in {-1,0,1}; sign only matters when od != 1.
    const float t  = fminf((od >= 2) ? zd : -zd, 1.0f);
    const float l1 = __logf(1.0f + __expf(-t));
    const float l2 = fmaxf(zd * zd, 1.0f);
    return (od == 1) ? l2 : l1;
}

// minBlocks=5 -> reg cap 51 (vs 40 at default 6): lets ptxas keep all 16
// gather addresses + results live, MLP_eff=16. Evidence R4 vs R8/R10: the
// 32-reg variant split the gather batch (MLP~8) and cost +7us despite
// higher occupancy. Warps beyond ~40/SM are not the binding resource.
__global__ __launch_bounds__(THREADS, 5) void rd_loss_kernel(
    const float* __restrict__ depth,
    const int*   __restrict__ xA,
    const int*   __restrict__ yA,
    const int*   __restrict__ xB,
    const int*   __restrict__ yB,
    const int*   __restrict__ ord,
    float* __restrict__ out)
{
    const int t  = blockIdx.x * THREADS + threadIdx.x;
    const int v0 = t;            // first vec4 group
    const int v1 = t + HALF;     // second vec4 group (coalesced within warp)

    // ---- Issue ALL index loads first (10 coalesced int4 LDGs in flight) ----
    const int4 xa0 = __ldg((const int4*)xA  + v0);
    const int4 ya0 = __ldg((const int4*)yA  + v0);
    const int4 xb0 = __ldg((const int4*)xB  + v0);
    const int4 yb0 = __ldg((const int4*)yB  + v0);
    const int4 od0 = __ldg((const int4*)ord + v0);
    const int4 xa1 = __ldg((const int4*)xA  + v1);
    const int4 ya1 = __ldg((const int4*)yA  + v1);
    const int4 xb1 = __ldg((const int4*)xB  + v1);
    const int4 yb1 = __ldg((const int4*)yB  + v1);
    const int4 od1 = __ldg((const int4*)ord + v1);

    // Batch index per group (4 consecutive points share a batch; P % 4 == 0).
    const float* __restrict__ base0 = depth + (long long)((v0 * 4) / P_DIM) * HW;
    const float* __restrict__ base1 = depth + (long long)((v1 * 4) / P_DIM) * HW;

    // ---- Issue ALL 16 gathers batched (max MLP) ----
    float zA[8], zB[8];
    zA[0] = __ldg(base0 + ya0.x * W_DIM + xa0.x);
    zA[1] = __ldg(base0 + ya0.y * W_DIM + xa0.y);
    zA[2] = __ldg(base0 + ya0.z * W_DIM + xa0.z);
    zA[3] = __ldg(base0 + ya0.w * W_DIM + xa0.w);
    zA[4] = __ldg(base1 + ya1.x * W_DIM + xa1.x);
    zA[5] = __ldg(base1 + ya1.y * W_DIM + xa1.y);
    zA[6] = __ldg(base1 + ya1.z * W_DIM + xa1.z);
    zA[7] = __ldg(base1 + ya1.w * W_DIM + xa1.w);
    zB[0] = __ldg(base0 + yb0.x * W_DIM + xb0.x);
    zB[1] = __ldg(base0 + yb0.y * W_DIM + xb0.y);
    zB[2] = __ldg(base0 + yb0.z * W_DIM + xb0.z);
    zB[3] = __ldg(base0 + yb0.w * W_DIM + xb0.w);
    zB[4] = __ldg(base1 + yb1.x * W_DIM + xb1.x);
    zB[5] = __ldg(base1 + yb1.y * W_DIM + xb1.y);
    zB[6] = __ldg(base1 + yb1.z * W_DIM + xb1.z);
    zB[7] = __ldg(base1 + yb1.w * W_DIM + xb1.w);

    // ---- Loss (two independent accumulation chains) ----
    float acc0 = 0.0f, acc1 = 0.0f;
    acc0 += loss_pt(zA[0], zB[0], od0.x);
    acc1 += loss_pt(zA[1], zB[1], od0.y);
    acc0 += loss_pt(zA[2], zB[2], od0.z);
    acc1 += loss_pt(zA[3], zB[3], od0.w);
    acc0 += loss_pt(zA[4], zB[4], od1.x);
    acc1 += loss_pt(zA[5], zB[5], od1.y);
    acc0 += loss_pt(zA[6], zB[6], od1.z);
    acc1 += loss_pt(zA[7], zB[7], od1.w);
    float acc = acc0 + acc1;

    // ---- Block reduction: warp shuffle, then smem across 8 warps ----
    __shared__ float warp_sums[THREADS / 32];
    const int lane = threadIdx.x & 31;
    const int wid  = threadIdx.x >> 5;
#pragma unroll
    for (int off = 16; off > 0; off >>= 1)
        acc += __shfl_xor_sync(0xFFFFFFFF, acc, off);
    if (lane == 0) warp_sums[wid] = acc;
    __syncthreads();

    if (threadIdx.x == 0) {
        float s = 0.0f;
#pragma unroll
        for (int w = 0; w < THREADS / 32; w++) s += warp_sums[w];

        // Accumulate into device scratch; last block finalizes and resets
        // the scratch so every graph replay starts from a clean state.
        atomicAdd(&g_partial, s);
        __threadfence();
        const unsigned done = atomicInc(&g_done, BLOCKS - 1);  // wraps to 0
        if (done == BLOCKS - 1) {
            const float total = atomicAdd(&g_partial, 0.0f);   // coherent read
            out[0] = total * (1.0f / (float)TOTAL);
            g_partial = 0.0f;                                  // reset for next replay
        }
    }
}

extern "C" void kernel_launch(void* const* d_in, const int* in_sizes, int n_in,
                              void* d_out, int out_size)
{
    const float* depth = (const float*)d_in[0];
    const int*   xA    = (const int*)d_in[1];
    const int*   yA    = (const int*)d_in[2];
    const int*   xB    = (const int*)d_in[3];
    const int*   yB    = (const int*)d_in[4];
    const int*   ord   = (const int*)d_in[5];
    float* out = (float*)d_out;

    rd_loss_kernel<<<BLOCKS, THREADS>>>(depth, xA, yA, xB, yB, ord, out);
}

// round 13
// speedup vs baseline: 1.0661x; 1.0352x over previous
#include <cuda_runtime.h>
#include <cuda_bf16.h>

// Problem constants (fixed by the reference).
#define B_DIM   64
#define H_DIM   512
#define W_DIM   640
#define P_DIM   100000
#define TOTAL   (B_DIM * P_DIM)     // 6,400,000 points
#define HW      (H_DIM * W_DIM)     // 327,680
#define NV4     (TOTAL / 4)         // 1,600,000 vec4 groups
#define HALF    (NV4 / 2)           // 800,000 vec4-pairs = total threads
#define THREADS 256
#define BLOCKS  (HALF / THREADS)    // 3125 (exact)

// Terminal configuration (R4). Measured evidence across 8 variants:
//  - 40 regs / 6 blocks / 48 warps per SM is the optimum; both more warps
//    (32 regs, 64 warps: +7us) and fewer (48-78 regs: +4us) regress.
//  - Plain __ldg everywhere; __ldcs costs up to +10us when index loads sit
//    on the critical path.
//  - One-shot grid beats grid-stride/pipelined loops (+3.5us loop tax).
// Wavefront floor: 552 L1tex wf/warp * 25k warps / 148 SMs ~= 93k cyc/SM
// ~= 52us @NAT; this kernel measures ~53.4us = 97% of floor.

// Cross-launch scratch for single-kernel finalization. Statically zero.
__device__ float        g_partial = 0.0f;
__device__ unsigned int g_done    = 0u;

__device__ __forceinline__ float loss_pt(float za, float zb, int od) {
    const float zd = za - zb;
    // gt = od-1 in {-1,0,1}; sign only matters when od != 1.
    const float t  = fminf((od >= 2) ? zd : -zd, 1.0f);
    const float l1 = __logf(1.0f + __expf(-t));
    const float l2 = fmaxf(zd * zd, 1.0f);
    return (od == 1) ? l2 : l1;
}

__global__ __launch_bounds__(THREADS) void rd_loss_kernel(
    const float* __restrict__ depth,
    const int*   __restrict__ xA,
    const int*   __restrict__ yA,
    const int*   __restrict__ xB,
    const int*   __restrict__ yB,
    const int*   __restrict__ ord,
    float* __restrict__ out)
{
    const int t  = blockIdx.x * THREADS + threadIdx.x;
    const int v0 = t;            // first vec4 group
    const int v1 = t + HALF;     // second vec4 group (coalesced within warp)

    // ---- Issue ALL index loads first (10 coalesced int4 LDGs in flight) ----
    const int4 xa0 = __ldg((const int4*)xA  + v0);
    const int4 ya0 = __ldg((const int4*)yA  + v0);
    const int4 xb0 = __ldg((const int4*)xB  + v0);
    const int4 yb0 = __ldg((const int4*)yB  + v0);
    const int4 od0 = __ldg((const int4*)ord + v0);
    const int4 xa1 = __ldg((const int4*)xA  + v1);
    const int4 ya1 = __ldg((const int4*)yA  + v1);
    const int4 xb1 = __ldg((const int4*)xB  + v1);
    const int4 yb1 = __ldg((const int4*)yB  + v1);
    const int4 od1 = __ldg((const int4*)ord + v1);

    // Batch index per group (4 consecutive points share a batch; P % 4 == 0).
    const float* __restrict__ base0 = depth + (long long)((v0 * 4) / P_DIM) * HW;
    const float* __restrict__ base1 = depth + (long long)((v1 * 4) / P_DIM) * HW;

    // ---- Issue ALL 16 gathers batched (max MLP) ----
    float zA[8], zB[8];
    zA[0] = __ldg(base0 + ya0.x * W_DIM + xa0.x);
    zA[1] = __ldg(base0 + ya0.y * W_DIM + xa0.y);
    zA[2] = __ldg(base0 + ya0.z * W_DIM + xa0.z);
    zA[3] = __ldg(base0 + ya0.w * W_DIM + xa0.w);
    zA[4] = __ldg(base1 + ya1.x * W_DIM + xa1.x);
    zA[5] = __ldg(base1 + ya1.y * W_DIM + xa1.y);
    zA[6] = __ldg(base1 + ya1.z * W_DIM + xa1.z);
    zA[7] = __ldg(base1 + ya1.w * W_DIM + xa1.w);
    zB[0] = __ldg(base0 + yb0.x * W_DIM + xb0.x);
    zB[1] = __ldg(base0 + yb0.y * W_DIM + xb0.y);
    zB[2] = __ldg(base0 + yb0.z * W_DIM + xb0.z);
    zB[3] = __ldg(base0 + yb0.w * W_DIM + xb0.w);
    zB[4] = __ldg(base1 + yb1.x * W_DIM + xb1.x);
    zB[5] = __ldg(base1 + yb1.y * W_DIM + xb1.y);
    zB[6] = __ldg(base1 + yb1.z * W_DIM + xb1.z);
    zB[7] = __ldg(base1 + yb1.w * W_DIM + xb1.w);

    // ---- Loss (two independent accumulation chains) ----
    float acc0 = 0.0f, acc1 = 0.0f;
    acc0 += loss_pt(zA[0], zB[0], od0.x);
    acc1 += loss_pt(zA[1], zB[1], od0.y);
    acc0 += loss_pt(zA[2], zB[2], od0.z);
    acc1 += loss_pt(zA[3], zB[3], od0.w);
    acc0 += loss_pt(zA[4], zB[4], od1.x);
    acc1 += loss_pt(zA[5], zB[5], od1.y);
    acc0 += loss_pt(zA[6], zB[6], od1.z);
    acc1 += loss_pt(zA[7], zB[7], od1.w);
    float acc = acc0 + acc1;

    // ---- Block reduction: warp shuffle, then smem across 8 warps ----
    __shared__ float warp_sums[THREADS / 32];
    const int lane = threadIdx.x & 31;
    const int wid  = threadIdx.x >> 5;
#pragma unroll
    for (int off = 16; off > 0; off >>= 1)
        acc += __shfl_xor_sync(0xFFFFFFFF, acc, off);
    if (lane == 0) warp_sums[wid] = acc;
    __syncthreads();

    if (threadIdx.x == 0) {
        float s = 0.0f;
#pragma unroll
        for (int w = 0; w < THREADS / 32; w++) s += warp_sums[w];

        // Accumulate into device scratch; last block finalizes and resets
        // the scratch so every graph replay starts from a clean state.
        atomicAdd(&g_partial, s);
        __threadfence();
        const unsigned done = atomicInc(&g_done, BLOCKS - 1);  // wraps to 0
        if (done == BLOCKS - 1) {
            const float total = atomicAdd(&g_partial, 0.0f);   // coherent read
            out[0] = total * (1.0f / (float)TOTAL);
            g_partial = 0.0f;                                  // reset for next replay
        }
    }
}

extern "C" void kernel_launch(void* const* d_in, const int* in_sizes, int n_in,
                              void* d_out, int out_size)
{
    const float* depth = (const float*)d_in[0];
    const int*   xA    = (const int*)d_in[1];
    const int*   yA    = (const int*)d_in[2];
    const int*   xB    = (const int*)d_in[3];
    const int*   yB    = (const int*)d_in[4];
    const int*   ord   = (const int*)d_in[5];
    float* out = (float*)d_out;

    rd_loss_kernel<<<BLOCKS, THREADS>>>(depth, xA, yA, xB, yB, ord, out);
}

// round 14
// speedup vs baseline: 1.0876x; 1.0202x over previous
#include <cuda_runtime.h>
#include <cuda_bf16.h>

// Problem constants (fixed by the reference).
#define B_DIM   64
#define H_DIM   512
#define W_DIM   640
#define P_DIM   100000
#define TOTAL   (B_DIM * P_DIM)     // 6,400,000 points
#define HW      (H_DIM * W_DIM)     // 327,680
#define NV4     (TOTAL / 4)         // 1,600,000 vec4 groups
#define HALF    (NV4 / 2)           // 800,000 vec4-pairs = total threads
#define THREADS 256
#define BLOCKS  (HALF / THREADS)    // 3125 (exact)

// Terminal configuration (validated over 9 structural variants, R4-R12):
//  - 40 regs / 48 warps per SM optimum; 32 regs+64 warps: +7us;
//    48-78 regs variants: +4us; 128-thread blocks: +11us.
//  - Plain __ldg everywhere (__ldcs: up to +10us on critical path).
//  - One-shot grid beats grid-stride/pipelined loops (+3.5us loop tax).
// Floor: 552 L1tex wavefronts/warp * 25k warps / 148 SMs ~= 93k cyc/SM
// ~= 52us @NAT; this kernel measures 53.4-55.9us = ~97% of floor.
// Run-to-run variance of this exact kernel measured at +/-2.5us.

// Cross-launch scratch for single-kernel finalization. Statically zero.
__device__ float        g_partial = 0.0f;
__device__ unsigned int g_done    = 0u;

__device__ __forceinline__ float loss_pt(float za, float zb, int od) {
    const float zd = za - zb;
    // gt = od-1 in {-1,0,1}; sign only matters when od != 1.
    const float t  = fminf((od >= 2) ? zd : -zd, 1.0f);
    const float l1 = __logf(1.0f + __expf(-t));
    const float l2 = fmaxf(zd * zd, 1.0f);
    return (od == 1) ? l2 : l1;
}

__global__ __launch_bounds__(THREADS) void rd_loss_kernel(
    const float* __restrict__ depth,
    const int*   __restrict__ xA,
    const int*   __restrict__ yA,
    const int*   __restrict__ xB,
    const int*   __restrict__ yB,
    const int*   __restrict__ ord,
    float* __restrict__ out)
{
    const int t  = blockIdx.x * THREADS + threadIdx.x;
    const int v0 = t;            // first vec4 group
    const int v1 = t + HALF;     // second vec4 group (coalesced within warp)

    // ---- Issue ALL index loads first (10 coalesced int4 LDGs in flight) ----
    const int4 xa0 = __ldg((const int4*)xA  + v0);
    const int4 ya0 = __ldg((const int4*)yA  + v0);
    const int4 xb0 = __ldg((const int4*)xB  + v0);
    const int4 yb0 = __ldg((const int4*)yB  + v0);
    const int4 od0 = __ldg((const int4*)ord + v0);
    const int4 xa1 = __ldg((const int4*)xA  + v1);
    const int4 ya1 = __ldg((const int4*)yA  + v1);
    const int4 xb1 = __ldg((const int4*)xB  + v1);
    const int4 yb1 = __ldg((const int4*)yB  + v1);
    const int4 od1 = __ldg((const int4*)ord + v1);

    // Batch index per group (4 consecutive points share a batch; P % 4 == 0).
    const float* __restrict__ base0 = depth + (long long)((v0 * 4) / P_DIM) * HW;
    const float* __restrict__ base1 = depth + (long long)((v1 * 4) / P_DIM) * HW;

    // ---- Issue ALL 16 gathers batched (max MLP) ----
    float zA[8], zB[8];
    zA[0] = __ldg(base0 + ya0.x * W_DIM + xa0.x);
    zA[1] = __ldg(base0 + ya0.y * W_DIM + xa0.y);
    zA[2] = __ldg(base0 + ya0.z * W_DIM + xa0.z);
    zA[3] = __ldg(base0 + ya0.w * W_DIM + xa0.w);
    zA[4] = __ldg(base1 + ya1.x * W_DIM + xa1.x);
    zA[5] = __ldg(base1 + ya1.y * W_DIM + xa1.y);
    zA[6] = __ldg(base1 + ya1.z * W_DIM + xa1.z);
    zA[7] = __ldg(base1 + ya1.w * W_DIM + xa1.w);
    zB[0] = __ldg(base0 + yb0.x * W_DIM + xb0.x);
    zB[1] = __ldg(base0 + yb0.y * W_DIM + xb0.y);
    zB[2] = __ldg(base0 + yb0.z * W_DIM + xb0.z);
    zB[3] = __ldg(base0 + yb0.w * W_DIM + xb0.w);
    zB[4] = __ldg(base1 + yb1.x * W_DIM + xb1.x);
    zB[5] = __ldg(base1 + yb1.y * W_DIM + xb1.y);
    zB[6] = __ldg(base1 + yb1.z * W_DIM + xb1.z);
    zB[7] = __ldg(base1 + yb1.w * W_DIM + xb1.w);

    // ---- Loss (two independent accumulation chains) ----
    float acc0 = 0.0f, acc1 = 0.0f;
    acc0 += loss_pt(zA[0], zB[0], od0.x);
    acc1 += loss_pt(zA[1], zB[1], od0.y);
    acc0 += loss_pt(zA[2], zB[2], od0.z);
    acc1 += loss_pt(zA[3], zB[3], od0.w);
    acc0 += loss_pt(zA[4], zB[4], od1.x);
    acc1 += loss_pt(zA[5], zB[5], od1.y);
    acc0 += loss_pt(zA[6], zB[6], od1.z);
    acc1 += loss_pt(zA[7], zB[7], od1.w);
    float acc = acc0 + acc1;

    // ---- Block reduction: warp shuffle, then smem across 8 warps ----
    __shared__ float warp_sums[THREADS / 32];
    const int lane = threadIdx.x & 31;
    const int wid  = threadIdx.x >> 5;
#pragma unroll
    for (int off = 16; off > 0; off >>= 1)
        acc += __shfl_xor_sync(0xFFFFFFFF, acc, off);
    if (lane == 0) warp_sums[wid] = acc;
    __syncthreads();

    if (threadIdx.x == 0) {
        float s = 0.0f;
#pragma unroll
        for (int w = 0; w < THREADS / 32; w++) s += warp_sums[w];

        // Fold 1/N here (free FMUL in parallel phase; exact same result as
        // dividing the total since it distributes over the sum linearly is
        // NOT exact -- so keep the division at the end for bit-faithfulness;
        // instead just accumulate raw sums).
        atomicAdd(&g_partial, s);
        __threadfence();
        const unsigned done = atomicInc(&g_done, BLOCKS - 1);  // wraps to 0
        if (done == BLOCKS - 1) {
            // All prior atomicAdds to g_partial are ordered before their
            // blocks' atomicInc; our fenced volatile load observes them all.
            const float total = *((volatile float*)&g_partial);
            out[0] = total * (1.0f / (float)TOTAL);
            g_partial = 0.0f;                                  // reset for next replay
        }
    }
}

extern "C" void kernel_launch(void* const* d_in, const int* in_sizes, int n_in,
                              void* d_out, int out_size)
{
    const float* depth = (const float*)d_in[0];
    const int*   xA    = (const int*)d_in[1];
    const int*   yA    = (const int*)d_in[2];
    const int*   xB    = (const int*)d_in[3];
    const int*   yB    = (const int*)d_in[4];
    const int*   ord   = (const int*)d_in[5];
    float* out = (float*)d_out;

    rd_loss_kernel<<<BLOCKS, THREADS>>>(depth, xA, yA, xB, yB, ord, out);
}

// round 15
// speedup vs baseline: 1.1044x; 1.0154x over previous
#include <cuda_runtime.h>
#include <cuda_bf16.h>

// Problem constants (fixed by the reference).
#define B_DIM   64
#define H_DIM   512
#define W_DIM   640
#define P_DIM   100000
#define TOTAL   (B_DIM * P_DIM)     // 6,400,000 points
#define HW      (H_DIM * W_DIM)     // 327,680
#define NV4     (TOTAL / 4)         // 1,600,000 vec4 groups
#define HALF    (NV4 / 2)           // 800,000 vec4-pairs = total threads
#define THREADS 256
#define BLOCKS  (HALF / THREADS)    // 3125 (exact)

// TERMINAL CONFIGURATION — validated over 10 structural variants (R4-R13):
//  - 40 regs / 6 blocks / 48 warps per SM is the optimum; 32 regs + 64
//    warps: +7us (gather batch split, MLP halved); 48-78 regs: +4us;
//    128-thread blocks: +11us (block refill churn).
//  - Plain __ldg everywhere (__ldcs adds unhidden latency: up to +10us).
//  - One-shot grid beats grid-stride/pipelined loops (+3.5us loop tax).
//  - Index pre-packing pre-pass: saves 2.9% main-kernel wavefronts, costs
//    ~20us of extra DRAM traffic. Rejected.
// Floor: 552 L1tex wavefronts/warp (40 index + 512 compulsory random-gather)
// * 25k warps / 148 SMs ~= 93k cyc/SM ~= 52us @NAT. This kernel samples
// 53.4 / 55.9 / 54.2 us ncu = ~96% of floor; residual is ramp/tail noise.

// Cross-launch scratch for single-kernel finalization. Statically zero.
__device__ float        g_partial = 0.0f;
__device__ unsigned int g_done    = 0u;

__device__ __forceinline__ float loss_pt(float za, float zb, int od) {
    const float zd = za - zb;
    // gt = od-1 in {-1,0,1}; sign only matters when od != 1.
    const float t  = fminf((od >= 2) ? zd : -zd, 1.0f);
    const float l1 = __logf(1.0f + __expf(-t));
    const float l2 = fmaxf(zd * zd, 1.0f);
    return (od == 1) ? l2 : l1;
}

__global__ __launch_bounds__(THREADS) void rd_loss_kernel(
    const float* __restrict__ depth,
    const int*   __restrict__ xA,
    const int*   __restrict__ yA,
    const int*   __restrict__ xB,
    const int*   __restrict__ yB,
    const int*   __restrict__ ord,
    float* __restrict__ out)
{
    const int t  = blockIdx.x * THREADS + threadIdx.x;
    const int v0 = t;            // first vec4 group
    const int v1 = t + HALF;     // second vec4 group (coalesced within warp)

    // ---- Issue ALL index loads first (10 coalesced int4 LDGs in flight) ----
    const int4 xa0 = __ldg((const int4*)xA  + v0);
    const int4 ya0 = __ldg((const int4*)yA  + v0);
    const int4 xb0 = __ldg((const int4*)xB  + v0);
    const int4 yb0 = __ldg((const int4*)yB  + v0);
    const int4 od0 = __ldg((const int4*)ord + v0);
    const int4 xa1 = __ldg((const int4*)xA  + v1);
    const int4 ya1 = __ldg((const int4*)yA  + v1);
    const int4 xb1 = __ldg((const int4*)xB  + v1);
    const int4 yb1 = __ldg((const int4*)yB  + v1);
    const int4 od1 = __ldg((const int4*)ord + v1);

    // Batch index per group (4 consecutive points share a batch; P % 4 == 0).
    const float* __restrict__ base0 = depth + (long long)((v0 * 4) / P_DIM) * HW;
    const float* __restrict__ base1 = depth + (long long)((v1 * 4) / P_DIM) * HW;

    // ---- Issue ALL 16 gathers batched (max MLP) ----
    float zA[8], zB[8];
    zA[0] = __ldg(base0 + ya0.x * W_DIM + xa0.x);
    zA[1] = __ldg(base0 + ya0.y * W_DIM + xa0.y);
    zA[2] = __ldg(base0 + ya0.z * W_DIM + xa0.z);
    zA[3] = __ldg(base0 + ya0.w * W_DIM + xa0.w);
    zA[4] = __ldg(base1 + ya1.x * W_DIM + xa1.x);
    zA[5] = __ldg(base1 + ya1.y * W_DIM + xa1.y);
    zA[6] = __ldg(base1 + ya1.z * W_DIM + xa1.z);
    zA[7] = __ldg(base1 + ya1.w * W_DIM + xa1.w);
    zB[0] = __ldg(base0 + yb0.x * W_DIM + xb0.x);
    zB[1] = __ldg(base0 + yb0.y * W_DIM + xb0.y);
    zB[2] = __ldg(base0 + yb0.z * W_DIM + xb0.z);
    zB[3] = __ldg(base0 + yb0.w * W_DIM + xb0.w);
    zB[4] = __ldg(base1 + yb1.x * W_DIM + xb1.x);
    zB[5] = __ldg(base1 + yb1.y * W_DIM + xb1.y);
    zB[6] = __ldg(base1 + yb1.z * W_DIM + xb1.z);
    zB[7] = __ldg(base1 + yb1.w * W_DIM + xb1.w);

    // ---- Loss (two independent accumulation chains) ----
    float acc0 = 0.0f, acc1 = 0.0f;
    acc0 += loss_pt(zA[0], zB[0], od0.x);
    acc1 += loss_pt(zA[1], zB[1], od0.y);
    acc0 += loss_pt(zA[2], zB[2], od0.z);
    acc1 += loss_pt(zA[3], zB[3], od0.w);
    acc0 += loss_pt(zA[4], zB[4], od1.x);
    acc1 += loss_pt(zA[5], zB[5], od1.y);
    acc0 += loss_pt(zA[6], zB[6], od1.z);
    acc1 += loss_pt(zA[7], zB[7], od1.w);
    float acc = acc0 + acc1;

    // ---- Block reduction: warp shuffle, then smem across 8 warps ----
    __shared__ float warp_sums[THREADS / 32];
    const int lane = threadIdx.x & 31;
    const int wid  = threadIdx.x >> 5;
#pragma unroll
    for (int off = 16; off > 0; off >>= 1)
        acc += __shfl_xor_sync(0xFFFFFFFF, acc, off);
    if (lane == 0) warp_sums[wid] = acc;
    __syncthreads();

    if (threadIdx.x == 0) {
        float s = 0.0f;
#pragma unroll
        for (int w = 0; w < THREADS / 32; w++) s += warp_sums[w];

        // Accumulate raw sums; divide once at the end (bit-faithful to ref).
        atomicAdd(&g_partial, s);
        __threadfence();
        const unsigned done = atomicInc(&g_done, BLOCKS - 1);  // wraps to 0
        if (done == BLOCKS - 1) {
            // All prior atomicAdds to g_partial are ordered before their
            // blocks' atomicInc; the fenced volatile load observes them all.
            const float total = *((volatile float*)&g_partial);
            out[0] = total * (1.0f / (float)TOTAL);
            g_partial = 0.0f;                                  // reset for next replay
        }
    }
}

extern "C" void kernel_launch(void* const* d_in, const int* in_sizes, int n_in,
                              void* d_out, int out_size)
{
    const float* depth = (const float*)d_in[0];
    const int*   xA    = (const int*)d_in[1];
    const int*   yA    = (const int*)d_in[2];
    const int*   xB    = (const int*)d_in[3];
    const int*   yB    = (const int*)d_in[4];
    const int*   ord   = (const int*)d_in[5];
    float* out = (float*)d_out;

    rd_loss_kernel<<<BLOCKS, THREADS>>>(depth, xA, yA, xB, yB, ord, out);
}